// round 13
// baseline (speedup 1.0000x reference)
#include <cuda_runtime.h>
#include <cstdint>
#include <math.h>

#define NT     512
#define PN     30
#define TP     33            // pair-row stride (in float2 units)
#define CIN    321
#define SEQ    720
#define NROW   480
#define ITEMS  5136
#define ISTR   21120
#define SCALEF 0.35355339059327373f   // 8^-0.5

typedef unsigned long long ull;

// persistent raw-score scratch: [item][t(30)][row(480)]
__device__ float scoG[(size_t)ITEMS * PN * NROW];

// ---------- packed f32x2 helpers ----------
__device__ __forceinline__ ull pk(float lo, float hi) {
    ull r; asm("mov.b64 %0, {%1, %2};" : "=l"(r) : "f"(lo), "f"(hi)); return r;
}
__device__ __forceinline__ float fin(ull a) {
    float x, y; asm("mov.b64 {%0, %1}, %2;" : "=f"(x), "=f"(y) : "l"(a)); return x + y;
}
__device__ __forceinline__ void up2(ull a, float& x, float& y) {
    asm("mov.b64 {%0, %1}, %2;" : "=f"(x), "=f"(y) : "l"(a));
}
__device__ __forceinline__ ull ffma2(ull a, ull b, ull c) {
    ull d; asm("fma.rn.f32x2 %0, %1, %2, %3;" : "=l"(d) : "l"(a), "l"(b), "l"(c)); return d;
}
__device__ __forceinline__ void ldg2(const float* p, ull& a, ull& b) {
    asm("ld.global.nc.v2.u64 {%0, %1}, [%2];" : "=l"(a), "=l"(b) : "l"(p));
}
__device__ __forceinline__ void lds2(uint32_t a32, ull& a, ull& b) {
    asm volatile("ld.shared.v2.u64 {%0, %1}, [%2];"
                 : "=l"(a), "=l"(b) : "r"(a32) : "memory");
}
// paired activation accessors: buffer holds [64 pairs][TP tokens] float2
__device__ __forceinline__ ull ldp(const float* b, int fp, int t) {
    return *(const ull*)(b + (fp*TP + t)*2);
}
__device__ __forceinline__ void stp(float* b, int fp, int t, ull v) {
    *(ull*)(b + (fp*TP + t)*2) = v;
}

// ---------- smem layout (floats) ----------
// per item (stride ISTR): xT 0 | prT 4224 | kT 8448 | vT 12672 | scr 16896
#define OFF_XT   0
#define OFF_PRT  4224
#define OFF_KT   8448
#define OFF_VT   12672
#define OFF_SCR  16896
#define OFF_STG  42240       // 16 warps x 512 floats (ring of 4 x 512B)
#define SMEM_FLOATS (42240 + 8192)
#define SMEM_BYTES  (SMEM_FLOATS * 4)    // 201,728 B -> 1 CTA/SM

// ---------- async weight staging: ring of 4 x 512B per warp, depth-2 prefetch ----------
__device__ __forceinline__ void fillc(uint32_t slot, const float* __restrict__ W,
                                      int f0, int ch, int buf, int lane) {
    int r = lane >> 2, o = lane & 3;
    uint32_t dst = slot + (uint32_t)(buf*512 + r*64 + o*16);
    const float* src = W + (size_t)(f0 + r)*128 + ch*16 + o*4;
    asm volatile("cp.async.cg.shared.global [%0], [%1], 16;"
                 :: "r"(dst), "l"(src) : "memory");
    asm volatile("cp.async.commit_group;" ::: "memory");
}
__device__ __forceinline__ void waitg2() {
    asm volatile("cp.async.wait_group 2;" ::: "memory");
    __syncwarp();
}
__device__ __forceinline__ void waitg1() {
    asm volatile("cp.async.wait_group 1;" ::: "memory");
    __syncwarp();
}
__device__ __forceinline__ void waitg0() {
    asm volatile("cp.async.wait_group 0;" ::: "memory");
    __syncwarp();
}

// warp computes 8 output features (rows f0..f0+7, K=128) for BOTH items.
// entry invariant: fills for Wc chunks 0 (buf0) and 1 (buf1) committed, <=2 pending.
// exit invariant (donext): fills for Wn chunks 0 (buf0) and 1 (buf1) committed.
__device__ __forceinline__ void accum8d2(const float* __restrict__ aA,
                                         const float* __restrict__ aB,
                                         const float* __restrict__ Wc,
                                         const float* __restrict__ Wn, bool donext,
                                         uint32_t slot, int f0, int lane,
                                         ull accA[8], ull accB[8]) {
    #pragma unroll
    for (int j = 0; j < 8; j++) { accA[j] = 0ULL; accB[j] = 0ULL; }
    #pragma unroll 1
    for (int ch = 0; ch < 8; ch++) {
        if (ch < 6)      { fillc(slot, Wc, f0, ch + 2, (ch + 2) & 3, lane); waitg2(); }
        else if (donext) { fillc(slot, Wn, f0, ch - 6, (ch + 2) & 3, lane); waitg2(); }
        else if (ch == 6)  waitg1();
        else               waitg0();

        ull apA[8], apB[8];
        #pragma unroll
        for (int j = 0; j < 8; j++) {
            apA[j] = ldp(aA, ch*8 + j, lane);
            apB[j] = ldp(aB, ch*8 + j, lane);
        }
        const uint32_t base = slot + (uint32_t)((ch & 3) * 512);
        #pragma unroll
        for (int f = 0; f < 8; f++) {
            uint32_t wr = base + (uint32_t)(f * 64);
            ull w0,w1,w2,w3,w4,w5,w6,w7;
            lds2(wr,      w0, w1);
            lds2(wr + 16, w2, w3);
            lds2(wr + 32, w4, w5);
            lds2(wr + 48, w6, w7);
            accA[f] = ffma2(apA[0], w0, accA[f]);
            accA[f] = ffma2(apA[1], w1, accA[f]);
            accA[f] = ffma2(apA[2], w2, accA[f]);
            accA[f] = ffma2(apA[3], w3, accA[f]);
            accA[f] = ffma2(apA[4], w4, accA[f]);
            accA[f] = ffma2(apA[5], w5, accA[f]);
            accA[f] = ffma2(apA[6], w6, accA[f]);
            accA[f] = ffma2(apA[7], w7, accA[f]);
            accB[f] = ffma2(apB[0], w0, accB[f]);
            accB[f] = ffma2(apB[1], w1, accB[f]);
            accB[f] = ffma2(apB[2], w2, accB[f]);
            accB[f] = ffma2(apB[3], w3, accB[f]);
            accB[f] = ffma2(apB[4], w4, accB[f]);
            accB[f] = ffma2(apB[5], w5, accB[f]);
            accB[f] = ffma2(apB[6], w6, accB[f]);
            accB[f] = ffma2(apB[7], w7, accB[f]);
        }
    }
}

// patch embedding: 8 features, K = 24 (12 pairs), dual item, weights via LDG
__device__ __forceinline__ void accum8p2(const float* __restrict__ aA,
                                         const float* __restrict__ aB,
                                         const float* __restrict__ w0,
                                         int lane, ull accA[8], ull accB[8]) {
    ull apA[12], apB[12];
    #pragma unroll
    for (int j = 0; j < 12; j++) {
        apA[j] = ldp(aA, j, lane);
        apB[j] = ldp(aB, j, lane);
    }
    #pragma unroll
    for (int f = 0; f < 8; f++) {
        const float* wr = w0 + f*24;
        accA[f] = 0ULL; accB[f] = 0ULL;
        #pragma unroll
        for (int q = 0; q < 6; q++) {
            ull wa, wb; ldg2(wr + 4*q, wa, wb);
            accA[f] = ffma2(apA[2*q],     wa, accA[f]);
            accA[f] = ffma2(apA[2*q + 1], wb, accA[f]);
            accB[f] = ffma2(apB[2*q],     wa, accB[f]);
            accB[f] = ffma2(apB[2*q + 1], wb, accB[f]);
        }
    }
}

// layernorm per item over feature dim (paired layout); tid2 = tid & 255
__device__ __forceinline__ void ln_T(float* bufT, const float* __restrict__ g,
                                     const float* __restrict__ be, float* red,
                                     int tid2) {
    const int t = tid2 & 31, w = tid2 >> 5;
    float vx[16]; float s = 0.f, q = 0.f;
    #pragma unroll
    for (int jj = 0; jj < 8; jj++) {
        ull vp = ldp(bufT, w*8 + jj, t);
        up2(vp, vx[2*jj], vx[2*jj+1]);
        s += vx[2*jj] + vx[2*jj+1];
        q += vx[2*jj]*vx[2*jj] + vx[2*jj+1]*vx[2*jj+1];
    }
    red[w*32 + t] = s; red[256 + w*32 + t] = q;
    __syncthreads();
    if (tid2 < 32) {
        float S = 0.f, Q = 0.f;
        #pragma unroll
        for (int r = 0; r < 8; r++) { S += red[r*32 + tid2]; Q += red[256 + r*32 + tid2]; }
        float m = S * (1.f/128.f);
        float var = Q * (1.f/128.f) - m*m;
        red[512 + tid2] = m;
        red[544 + tid2] = rsqrtf(var + 1e-5f);
    }
    __syncthreads();
    const float m = red[512 + t], rr = red[544 + t];
    #pragma unroll
    for (int jj = 0; jj < 8; jj++) {
        int d0 = w*16 + 2*jj;
        float y0 = (vx[2*jj]   - m)*rr*g[d0]   + be[d0];
        float y1 = (vx[2*jj+1] - m)*rr*g[d0+1] + be[d0+1];
        stp(bufT, w*8 + jj, t, pk(y0, y1));
    }
}

__global__ __launch_bounds__(NT, 1)
void ts_kernel(const float* __restrict__ z,
               const float* __restrict__ WPw, const float* __restrict__ WPb,
               const float* __restrict__ PE,  const float* __restrict__ dummies,
               const float* __restrict__ Wq,  const float* __restrict__ bq,
               const float* __restrict__ Wk,  const float* __restrict__ bk,
               const float* __restrict__ Wv,  const float* __restrict__ bv,
               const float* __restrict__ Wo,  const float* __restrict__ bo,
               const float* __restrict__ g1,  const float* __restrict__ be1,
               const float* __restrict__ W1,  const float* __restrict__ b1,
               const float* __restrict__ W2,  const float* __restrict__ b2,
               const float* __restrict__ g2,  const float* __restrict__ be2,
               const float* __restrict__ Pw,  const float* __restrict__ Pb,
               float* __restrict__ out)
{
    extern __shared__ float sm[];
    float* xT  = sm + OFF_XT;
    float* prT = sm + OFF_PRT;
    float* kT  = sm + OFF_KT;
    float* vT  = sm + OFF_VT;
    float* scr = sm + OFF_SCR;

    const int tid  = threadIdx.x;
    const int wid  = tid >> 5;
    const int lane = tid & 31;
    const int f0   = wid * 8;
    const int fp0  = wid * 4;
    const int blk  = blockIdx.x;

    const int half = tid >> 8;
    const int tid2 = tid & 255;
    const int item = blk*2 + half;
    const int chn  = item % CIN;
    const float* zr = z + (size_t)item * SEQ;
    float* hb = sm + half * ISTR;

    const uint32_t slot =
        (uint32_t)__cvta_generic_to_shared(sm + OFF_STG) + (uint32_t)wid * 2048u;

    // prefetch layer-0 Wk chunks 0,1 -> bufs 0,1
    fillc(slot, Wk, f0, 0, 0, lane);
    fillc(slot, Wk, f0, 1, 1, lane);

    // -------- instance stats (per item) --------
    float* redh = hb + OFF_SCR;
    float s1 = 0.f, s2 = 0.f;
    for (int i = tid2; i < SEQ; i += 256) { float v = zr[i]; s1 += v; s2 += v*v; }
    #pragma unroll
    for (int o = 16; o; o >>= 1) {
        s1 += __shfl_xor_sync(0xffffffffu, s1, o);
        s2 += __shfl_xor_sync(0xffffffffu, s2, o);
    }
    if (lane == 0) { redh[tid2 >> 5] = s1; redh[8 + (tid2 >> 5)] = s2; }
    __syncthreads();
    if (tid2 == 0) {
        float S1 = 0.f, S2 = 0.f;
        #pragma unroll
        for (int w = 0; w < 8; w++) { S1 += redh[w]; S2 += redh[8 + w]; }
        float m   = S1 / (float)SEQ;
        float var = S2 / (float)SEQ - m*m;
        float sd  = sqrtf(var + 1e-5f);
        redh[16] = m; redh[17] = 1.f/sd; redh[18] = sd;
    }
    __syncthreads();
    const float mu = redh[16], rstd = redh[17], sd = redh[18];
    __syncthreads();

    // -------- stage znT patches (paired) into item's vT; PE into item-A kT --------
    for (int i = tid2; i < SEQ; i += 256) {
        int s = i / 24, p = i - s*24;
        hb[OFF_VT + ((p>>1)*TP + s)*2 + (p&1)] = (zr[i] - mu) * rstd;
    }
    for (int i = tid; i < PN*128; i += NT) {
        int s = i >> 7, d = i & 127;
        kT[((d>>1)*TP + s)*2 + (d&1)] = PE[i];
    }
    __syncthreads();

    // -------- patch embedding: x = W_P*patches + b + PE (dual) --------
    {
        ull aA[8], aB[8];
        accum8p2(vT, vT + ISTR, WPw + f0*24, lane, aA, aB);
        if (lane < PN) {
            #pragma unroll
            for (int j = 0; j < 4; j++) {
                float pe0, pe1; up2(ldp(kT, fp0 + j, lane), pe0, pe1);
                float b0 = WPb[f0 + 2*j], b1v = WPb[f0 + 2*j + 1];
                stp(xT,        fp0 + j, lane, pk(fin(aA[2*j]) + b0 + pe0, fin(aA[2*j+1]) + b1v + pe1));
                stp(xT + ISTR, fp0 + j, lane, pk(fin(aB[2*j]) + b0 + pe0, fin(aB[2*j+1]) + b1v + pe1));
            }
        }
    }
    __syncthreads();
    // -------- pred from dummies --------
    {
        const float* dm = dummies + (size_t)chn * PN * 24;
        for (int i = tid2; i < PN*24; i += 256) {
            int s = i / 24, p = i - s*24;
            hb[OFF_VT + ((p>>1)*TP + s)*2 + (p&1)] = dm[i];
        }
        __syncthreads();
        ull aA[8], aB[8];
        accum8p2(vT, vT + ISTR, WPw + f0*24, lane, aA, aB);
        if (lane < PN) {
            #pragma unroll
            for (int j = 0; j < 4; j++) {
                float b0 = WPb[f0 + 2*j], b1v = WPb[f0 + 2*j + 1];
                stp(prT,        fp0 + j, lane, pk(fin(aA[2*j]) + b0, fin(aA[2*j+1]) + b1v));
                stp(prT + ISTR, fp0 + j, lane, pk(fin(aB[2*j]) + b0, fin(aB[2*j+1]) + b1v));
            }
        }
    }
    __syncthreads();

    // -------- transformer layers --------
    #pragma unroll 1
    for (int L = 0; L < 3; L++) {
        const size_t o128 = (size_t)L * 16384;
        const float* w1a = W1 + (size_t)L * 32768;
        const float* w1g = w1a + 16384;

        // ---- K ----
        {
            ull aA[8], aB[8];
            accum8d2(xT, xT + ISTR, Wk + o128, Wv + o128, true, slot, f0, lane, aA, aB);
            if (lane < PN) {
                #pragma unroll
                for (int j = 0; j < 4; j++) {
                    float b0 = bk[L*128 + f0 + 2*j], b1v = bk[L*128 + f0 + 2*j + 1];
                    stp(kT,        fp0 + j, lane, pk(fin(aA[2*j]) + b0, fin(aA[2*j+1]) + b1v));
                    stp(kT + ISTR, fp0 + j, lane, pk(fin(aB[2*j]) + b0, fin(aB[2*j+1]) + b1v));
                }
            }
        }
        // ---- V ----
        {
            ull aA[8], aB[8];
            accum8d2(xT, xT + ISTR, Wv + o128, Wq + o128, true, slot, f0, lane, aA, aB);
            if (lane < PN) {
                #pragma unroll
                for (int j = 0; j < 4; j++) {
                    float b0 = bv[L*128 + f0 + 2*j], b1v = bv[L*128 + f0 + 2*j + 1];
                    stp(vT,        fp0 + j, lane, pk(fin(aA[2*j]) + b0, fin(aA[2*j+1]) + b1v));
                    stp(vT + ISTR, fp0 + j, lane, pk(fin(aB[2*j]) + b0, fin(aB[2*j+1]) + b1v));
                }
            }
        }
        // ---- Q -> scr ----
        {
            ull aA[8], aB[8];
            accum8d2(prT, prT + ISTR, Wq + o128, Wo + o128, true, slot, f0, lane, aA, aB);
            if (lane < PN) {
                #pragma unroll
                for (int j = 0; j < 4; j++) {
                    float b0 = bq[L*128 + f0 + 2*j], b1v = bq[L*128 + f0 + 2*j + 1];
                    stp(scr,        fp0 + j, lane, pk(fin(aA[2*j]) + b0, fin(aA[2*j+1]) + b1v));
                    stp(scr + ISTR, fp0 + j, lane, pk(fin(aB[2*j]) + b0, fin(aB[2*j+1]) + b1v));
                }
            }
        }
        __syncthreads();

        // ---- attention: thread per (h,p,item); scores kept in registers ----
        for (int rr = tid; rr < 2*NROW; rr += NT) {
            const int it = rr >= NROW;
            const int r0 = rr - it*NROW;
            const int h = r0 / PN, p = r0 - h*PN;
            float* ib = sm + it * ISTR;
            float* sg = scoG + (size_t)(blk*2 + it) * (PN*NROW) + r0;
            ull qp[4];
            #pragma unroll
            for (int jj = 0; jj < 4; jj++) qp[jj] = ldp(ib + OFF_SCR, h*4 + jj, p);
            float sreg[PN];
            float m = -1e30f;
            #pragma unroll
            for (int t = 0; t < PN; t++) {
                ull d2 = 0ULL;
                #pragma unroll
                for (int jj = 0; jj < 4; jj++)
                    d2 = ffma2(qp[jj], ldp(ib + OFF_KT, h*4 + jj, t), d2);
                float s = fin(d2) * SCALEF;
                if (L) s += sg[t*NROW];
                sg[t*NROW] = s;
                sreg[t] = s;
                m = fmaxf(m, s);
            }
            float ssum = 0.f;
            #pragma unroll
            for (int t = 0; t < PN; t++) {
                float w = __expf(sreg[t] - m);
                sreg[t] = w;
                ssum += w;
            }
            const float inv = 1.f / ssum;
            ull ov[4];
            #pragma unroll
            for (int jj = 0; jj < 4; jj++) ov[jj] = 0ULL;
            #pragma unroll
            for (int t = 0; t < PN; t++) {
                ull wp = pk(sreg[t], sreg[t]);
                #pragma unroll
                for (int jj = 0; jj < 4; jj++)
                    ov[jj] = ffma2(wp, ldp(ib + OFF_VT, h*4 + jj, t), ov[jj]);
            }
            #pragma unroll
            for (int jj = 0; jj < 4; jj++) {
                float o0, o1; up2(ov[jj], o0, o1);
                stp(ib + OFF_SCR, h*4 + jj, p, pk(o0*inv, o1*inv));
            }
        }
        __syncthreads();

        // ---- O + residual ----
        {
            ull aA[8], aB[8];
            accum8d2(scr, scr + ISTR, Wo + o128, w1a, true, slot, f0, lane, aA, aB);
            if (lane < PN) {
                #pragma unroll
                for (int j = 0; j < 4; j++) {
                    float b0 = bo[L*128 + f0 + 2*j], b1v = bo[L*128 + f0 + 2*j + 1];
                    float pA0, pA1, pB0, pB1;
                    up2(ldp(prT,        fp0 + j, lane), pA0, pA1);
                    up2(ldp(prT + ISTR, fp0 + j, lane), pB0, pB1);
                    stp(prT,        fp0 + j, lane, pk(pA0 + fin(aA[2*j]) + b0, pA1 + fin(aA[2*j+1]) + b1v));
                    stp(prT + ISTR, fp0 + j, lane, pk(pB0 + fin(aB[2*j]) + b0, pB1 + fin(aB[2*j+1]) + b1v));
                }
            }
        }
        __syncthreads();
        ln_T(hb + OFF_PRT, g1 + L*128, be1 + L*128, hb + OFF_SCR, tid2);
        __syncthreads();

        // ---- FFN up a-half -> vT ----
        {
            ull aA[8], aB[8];
            accum8d2(prT, prT + ISTR, w1a, w1g, true, slot, f0, lane, aA, aB);
            if (lane < PN) {
                #pragma unroll
                for (int j = 0; j < 4; j++) {
                    float b0 = b1[L*256 + f0 + 2*j], b1v = b1[L*256 + f0 + 2*j + 1];
                    stp(vT,        fp0 + j, lane, pk(fin(aA[2*j]) + b0, fin(aA[2*j+1]) + b1v));
                    stp(vT + ISTR, fp0 + j, lane, pk(fin(aB[2*j]) + b0, fin(aB[2*j+1]) + b1v));
                }
            }
        }
        // ---- FFN up gate-half; gelu combine -> kT ----
        {
            ull aA[8], aB[8];
            accum8d2(prT, prT + ISTR, w1g, W2 + o128, true, slot, f0, lane, aA, aB);
            if (lane < PN) {
                #pragma unroll
                for (int j = 0; j < 4; j++) {
                    float b0 = b1[L*256 + 128 + f0 + 2*j], b1v = b1[L*256 + 128 + f0 + 2*j + 1];
                    float gA0 = fin(aA[2*j]) + b0,  gA1 = fin(aA[2*j+1]) + b1v;
                    float gB0 = fin(aB[2*j]) + b0,  gB1 = fin(aB[2*j+1]) + b1v;
                    float eA0 = 0.5f*gA0*(1.f + erff(gA0*0.70710678118654752f));
                    float eA1 = 0.5f*gA1*(1.f + erff(gA1*0.70710678118654752f));
                    float eB0 = 0.5f*gB0*(1.f + erff(gB0*0.70710678118654752f));
                    float eB1 = 0.5f*gB1*(1.f + erff(gB1*0.70710678118654752f));
                    float vA0, vA1, vB0, vB1;
                    up2(ldp(vT,        fp0 + j, lane), vA0, vA1);
                    up2(ldp(vT + ISTR, fp0 + j, lane), vB0, vB1);
                    stp(kT,        fp0 + j, lane, pk(vA0*eA0, vA1*eA1));
                    stp(kT + ISTR, fp0 + j, lane, pk(vB0*eB0, vB1*eB1));
                }
            }
        }
        __syncthreads();

        // ---- FFN down + residual ----
        {
            ull aA[8], aB[8];
            accum8d2(kT, kT + ISTR, W2 + o128, Wk + (size_t)(L+1)*16384, L < 2,
                     slot, f0, lane, aA, aB);
            if (lane < PN) {
                #pragma unroll
                for (int j = 0; j < 4; j++) {
                    float b0 = b2[L*128 + f0 + 2*j], b1v = b2[L*128 + f0 + 2*j + 1];
                    float pA0, pA1, pB0, pB1;
                    up2(ldp(prT,        fp0 + j, lane), pA0, pA1);
                    up2(ldp(prT + ISTR, fp0 + j, lane), pB0, pB1);
                    stp(prT,        fp0 + j, lane, pk(pA0 + fin(aA[2*j]) + b0, pA1 + fin(aA[2*j+1]) + b1v));
                    stp(prT + ISTR, fp0 + j, lane, pk(pB0 + fin(aB[2*j]) + b0, pB1 + fin(aB[2*j+1]) + b1v));
                }
            }
        }
        __syncthreads();
        ln_T(hb + OFF_PRT, g2 + L*128, be2 + L*128, hb + OFF_SCR, tid2);
        __syncthreads();
    }

    // -------- output head: warp-halves per item, 3 patch-lanes/warp --------
    {
        const int hit  = wid >> 3;
        const int pl0  = (wid & 7) * 3;
        const float* pT = sm + hit*ISTR + OFF_PRT;
        float* outb     = sm + hit*ISTR + OFF_SCR;
        ull a0 = 0ULL, a1 = 0ULL, a2 = 0ULL;
        #pragma unroll 2
        for (int c = 0; c < 8; c++) {
            ull ap[8];
            #pragma unroll
            for (int j = 0; j < 8; j++)
                ap[j] = ldp(pT, c*8 + j, lane);
            const float* wr0 = Pw + (pl0    )*128 + c*16;
            const float* wr1 = Pw + (pl0 + 1)*128 + c*16;
            const float* wr2 = Pw + (pl0 + 2)*128 + c*16;
            #pragma unroll
            for (int q = 0; q < 4; q++) {
                ull wa, wb;
                ldg2(wr0 + 4*q, wa, wb);
                a0 = ffma2(ap[2*q], wa, a0); a0 = ffma2(ap[2*q+1], wb, a0);
                ldg2(wr1 + 4*q, wa, wb);
                a1 = ffma2(ap[2*q], wa, a1); a1 = ffma2(ap[2*q+1], wb, a1);
                ldg2(wr2 + 4*q, wa, wb);
                a2 = ffma2(ap[2*q], wa, a2); a2 = ffma2(ap[2*q+1], wb, a2);
            }
        }
        if (lane < PN) {
            outb[lane*24 + pl0    ] = fin(a0) + Pb[pl0];
            outb[lane*24 + pl0 + 1] = fin(a1) + Pb[pl0 + 1];
            outb[lane*24 + pl0 + 2] = fin(a2) + Pb[pl0 + 2];
        }
    }
    __syncthreads();
    {
        const float* outb = hb + OFF_SCR;
        for (int i = tid2; i < SEQ; i += 256)
            out[(size_t)item*SEQ + i] = outb[i]*sd + mu;
    }
}

extern "C" void kernel_launch(void* const* d_in, const int* in_sizes, int n_in,
                              void* d_out, int out_size)
{
    (void)in_sizes; (void)n_in; (void)out_size;
    cudaFuncSetAttribute(ts_kernel, cudaFuncAttributeMaxDynamicSharedMemorySize, SMEM_BYTES);
    ts_kernel<<<ITEMS/2, NT, SMEM_BYTES>>>(
        (const float*)d_in[0],  (const float*)d_in[1],  (const float*)d_in[2],
        (const float*)d_in[3],  (const float*)d_in[4],  (const float*)d_in[5],
        (const float*)d_in[6],  (const float*)d_in[7],  (const float*)d_in[8],
        (const float*)d_in[9],  (const float*)d_in[10], (const float*)d_in[11],
        (const float*)d_in[12], (const float*)d_in[13], (const float*)d_in[14],
        (const float*)d_in[15], (const float*)d_in[16], (const float*)d_in[17],
        (const float*)d_in[18], (const float*)d_in[19], (const float*)d_in[20],
        (const float*)d_in[21], (const float*)d_in[22],
        (float*)d_out);
}